// round 8
// baseline (speedup 1.0000x reference)
#include <cuda_runtime.h>
#include <cstdint>

#define HW 480
#define KP 24
#define PGRID 20          // 480/24
#define NP 400            // patches
#define NC 3
#define PS 1728           // 3*24*24
#define HC 457            // 480-24+1
#define SIGMA 1e-6f
#define IMG (HW*HW)       // 230400 per channel
#define YPITCH 488        // smem row pitch (floats), %4==0, covers c0max(456)+31=487
#define YROWS 31          // 8 tile rows + 23
#define ROWS_PER_BLK 8
#define THREADS_C 512

__device__ float g_patch[NP * PS];
__device__ float g_meanx[NP];
__device__ float g_denx[NP];
__device__ float g_colsum[HC * HW];
__device__ float g_colsum2[HC * HW];
__device__ float g_sy[HC * HC];
__device__ float g_dy[HC * HC];
__device__ unsigned long long g_best[NP];

// ---------------- Kernel A: patch extraction + stats + best reset ----------------
__global__ void k_prep(const float* __restrict__ x) {
    int p = blockIdx.x, tid = threadIdx.x;
    int pr = p / PGRID, pc = p % PGRID;
    float s = 0.f, s2 = 0.f;
    for (int e = tid; e < PS; e += 256) {
        int ch = e / 576, rem = e % 576;
        int i = rem / KP, j = rem % KP;
        float v = x[ch * IMG + (pr * KP + i) * HW + (pc * KP + j)];
        g_patch[p * PS + e] = v;
        s += v; s2 += v * v;
    }
    __shared__ float rs[256], rs2[256];
    rs[tid] = s; rs2[tid] = s2;
    __syncthreads();
    for (int off = 128; off > 0; off >>= 1) {
        if (tid < off) { rs[tid] += rs[tid + off]; rs2[tid] += rs2[tid + off]; }
        __syncthreads();
    }
    if (tid == 0) {
        float mean = rs[0] * (1.f / PS);
        g_meanx[p] = mean;
        g_denx[p] = fabsf(rs2[0] * (1.f / PS) - mean * mean);
        g_best[p] = 0ull;
    }
}

// ---------------- Kernel B1: vertical 24-row column sums over all channels ------
__global__ void k_colsum(const float* __restrict__ yd) {
    int idx = blockIdx.x * blockDim.x + threadIdx.x;
    if (idx >= HC * HW) return;
    int r = idx / HW, c = idx % HW;
    float s = 0.f, s2 = 0.f;
    for (int ch = 0; ch < NC; ch++) {
        const float* base = yd + ch * IMG + r * HW + c;
        #pragma unroll
        for (int i = 0; i < KP; i++) {
            float v = base[i * HW];
            s += v; s2 += v * v;
        }
    }
    g_colsum[idx] = s;
    g_colsum2[idx] = s2;
}

// ---------------- Kernel B2: horizontal 24-col sums -> sy, |den_y| --------------
__global__ void k_symap() {
    int idx = blockIdx.x * blockDim.x + threadIdx.x;
    if (idx >= HC * HC) return;
    int r = idx / HC, c = idx % HC;
    const float* cs = g_colsum + r * HW + c;
    const float* cs2 = g_colsum2 + r * HW + c;
    float s = 0.f, s2 = 0.f;
    #pragma unroll
    for (int j = 0; j < KP; j++) { s += cs[j]; s2 += cs2[j]; }
    const float inv = 1.f / PS;
    g_sy[idx] = s;
    g_dy[idx] = fabsf(s2 * inv - s * s * inv * inv);
}

// ---------------- Kernel C: correlation + per-patch argmax ----------------------
// grid = (400, 58). block = 512 threads = 8 rows x 64 col-groups of 8 columns.
__global__ void __launch_bounds__(THREADS_C) k_corr(const float* __restrict__ yd) {
    int p = blockIdx.x;
    int r0 = blockIdx.y * ROWS_PER_BLK;
    int tid = threadIdx.x;
    int row_in = tid >> 6;        // 0..7
    int cg = tid & 63;            // 0..63
    int c0 = cg << 3;             // 0..504
    int r = r0 + row_in;
    bool active = (r < HC) && (c0 < HC);

    extern __shared__ float ytile[];          // YROWS * YPITCH
    __shared__ float wpat[576];
    __shared__ unsigned long long red[16];

    float acc[8];
    #pragma unroll
    for (int t = 0; t < 8; t++) acc[t] = 0.f;

    for (int ch = 0; ch < NC; ch++) {
        __syncthreads();
        // patch channel slice -> smem
        for (int e = tid; e < 576; e += THREADS_C)
            wpat[e] = g_patch[p * PS + ch * 576 + e];
        // y tile (rows r0..r0+30, cols 0..487 with 0-pad) -> smem
        const float* yb = yd + ch * IMG;
        for (int e = tid; e < YROWS * YPITCH; e += THREADS_C) {
            int rr = e / YPITCH, cc = e - rr * YPITCH;
            int gr = r0 + rr;
            ytile[e] = (gr < HW && cc < HW) ? yb[gr * HW + cc] : 0.f;
        }
        __syncthreads();

        if (active) {
            #pragma unroll 2
            for (int i = 0; i < KP; i++) {
                const float4* yv = (const float4*)(ytile + (row_in + i) * YPITCH + c0);
                float yw[32];
                #pragma unroll
                for (int q = 0; q < 8; q++) {
                    float4 v = yv[q];
                    yw[4 * q + 0] = v.x; yw[4 * q + 1] = v.y;
                    yw[4 * q + 2] = v.z; yw[4 * q + 3] = v.w;
                }
                const float4* wv = (const float4*)(wpat + i * KP);
                #pragma unroll
                for (int jj = 0; jj < 6; jj++) {
                    float4 w = wv[jj];
                    #pragma unroll
                    for (int t = 0; t < 8; t++) {
                        acc[t] = fmaf(w.x, yw[4 * jj + 0 + t], acc[t]);
                        acc[t] = fmaf(w.y, yw[4 * jj + 1 + t], acc[t]);
                        acc[t] = fmaf(w.z, yw[4 * jj + 2 + t], acc[t]);
                        acc[t] = fmaf(w.w, yw[4 * jj + 3 + t], acc[t]);
                    }
                }
            }
        }
    }

    // epilogue: corr + packed argmax key
    unsigned long long bk = 0ull;
    if (active) {
        float mx = g_meanx[p];
        float dxa = g_denx[p];
        const float invps = 1.f / PS;
        #pragma unroll
        for (int t = 0; t < 8; t++) {
            int c = c0 + t;
            if (c < HC) {
                int pos = r * HC + c;
                float s = g_sy[pos];
                float dya = g_dy[pos];
                float corr = (2.f * (acc[t] - mx * s) * invps + SIGMA) / (dxa + dya + SIGMA);
                unsigned u = __float_as_uint(corr);
                u = (u & 0x80000000u) ? ~u : (u | 0x80000000u);
                unsigned long long key =
                    ((unsigned long long)u << 32) | (unsigned long long)(~(unsigned)pos);
                if (key > bk) bk = key;
            }
        }
    }
    // warp reduce
    #pragma unroll
    for (int off = 16; off > 0; off >>= 1) {
        unsigned long long o = __shfl_down_sync(0xffffffffu, bk, off);
        if (o > bk) bk = o;
    }
    int warp = tid >> 5, lane = tid & 31;
    if (lane == 0) red[warp] = bk;
    __syncthreads();
    if (tid == 0) {
        unsigned long long b = red[0];
        #pragma unroll
        for (int w = 1; w < 16; w++) if (red[w] > b) b = red[w];
        atomicMax(&g_best[p], b);
    }
}

// ---------------- Kernel D: gather winning patches from y, fold to image --------
__global__ void k_gather(const float* __restrict__ y, float* __restrict__ out) {
    int idx = blockIdx.x * blockDim.x + threadIdx.x;
    if (idx >= NC * IMG) return;
    int ch = idx / IMG, rem = idx % IMG;
    int h = rem / HW, w = rem % HW;
    int p = (h / KP) * PGRID + (w / KP);
    unsigned pos = ~((unsigned)(g_best[p] & 0xffffffffull));
    int rp = pos / HC, cp = pos % HC;
    out[idx] = y[ch * IMG + (rp + h % KP) * HW + (cp + w % KP)];
}

extern "C" void kernel_launch(void* const* d_in, const int* in_sizes, int n_in,
                              void* d_out, int out_size) {
    const float* x_dec = (const float*)d_in[0];
    const float* y_dec = (const float*)d_in[1];
    const float* y     = (const float*)d_in[2];
    float* out = (float*)d_out;

    const int smem_c = YROWS * YPITCH * sizeof(float);   // 60512 bytes
    cudaFuncSetAttribute(k_corr, cudaFuncAttributeMaxDynamicSharedMemorySize, smem_c);

    k_prep<<<NP, 256>>>(x_dec);
    k_colsum<<<(HC * HW + 255) / 256, 256>>>(y_dec);
    k_symap<<<(HC * HC + 255) / 256, 256>>>();
    dim3 gc(NP, (HC + ROWS_PER_BLK - 1) / ROWS_PER_BLK);   // (400, 58)
    k_corr<<<gc, THREADS_C, smem_c>>>(y_dec);
    k_gather<<<(NC * IMG + 255) / 256, 256>>>(y, out);
}

// round 10
// speedup vs baseline: 1.0583x; 1.0583x over previous
#include <cuda_runtime.h>
#include <cstdint>

#define HW 480
#define KP 24
#define PGRID 20          // 480/24
#define NP 400            // patches
#define NC 3
#define PS 1728           // 3*24*24
#define HC 457            // 480-24+1
#define SIGMA 1e-6f
#define IMG (HW*HW)       // 230400 per channel
#define YPITCH 488        // smem row pitch (floats), %4==0, covers c0max(456)+31=487
#define YROWS 31          // 8 tile rows + 23
#define ROWS_PER_BLK 8
#define THREADS_C 512

__device__ float g_patch[NP * PS];
__device__ float g_meanx[NP];
__device__ float g_denx[NP];
__device__ float g_colsum[HC * HW];
__device__ float g_colsum2[HC * HW];
__device__ float g_sy[HC * HC];
__device__ float g_dy[HC * HC];
__device__ unsigned long long g_best[NP];

// ---------------- Kernel A: patch extraction + stats + best reset ----------------
__global__ void k_prep(const float* __restrict__ x) {
    int p = blockIdx.x, tid = threadIdx.x;
    int pr = p / PGRID, pc = p % PGRID;
    float s = 0.f, s2 = 0.f;
    for (int e = tid; e < PS; e += 256) {
        int ch = e / 576, rem = e % 576;
        int i = rem / KP, j = rem % KP;
        float v = x[ch * IMG + (pr * KP + i) * HW + (pc * KP + j)];
        g_patch[p * PS + e] = v;
        s += v; s2 += v * v;
    }
    __shared__ float rs[256], rs2[256];
    rs[tid] = s; rs2[tid] = s2;
    __syncthreads();
    for (int off = 128; off > 0; off >>= 1) {
        if (tid < off) { rs[tid] += rs[tid + off]; rs2[tid] += rs2[tid + off]; }
        __syncthreads();
    }
    if (tid == 0) {
        float mean = rs[0] * (1.f / PS);
        g_meanx[p] = mean;
        g_denx[p] = fabsf(rs2[0] * (1.f / PS) - mean * mean);
        g_best[p] = 0ull;
    }
}

// ---------------- Kernel B1: vertical 24-row column sums over all channels ------
__global__ void k_colsum(const float* __restrict__ yd) {
    int idx = blockIdx.x * blockDim.x + threadIdx.x;
    if (idx >= HC * HW) return;
    int r = idx / HW, c = idx % HW;
    float s = 0.f, s2 = 0.f;
    for (int ch = 0; ch < NC; ch++) {
        const float* base = yd + ch * IMG + r * HW + c;
        #pragma unroll
        for (int i = 0; i < KP; i++) {
            float v = base[i * HW];
            s += v; s2 += v * v;
        }
    }
    g_colsum[idx] = s;
    g_colsum2[idx] = s2;
}

// ---------------- Kernel B2: horizontal 24-col sums -> sy, |den_y| --------------
__global__ void k_symap() {
    int idx = blockIdx.x * blockDim.x + threadIdx.x;
    if (idx >= HC * HC) return;
    int r = idx / HC, c = idx % HC;
    const float* cs = g_colsum + r * HW + c;
    const float* cs2 = g_colsum2 + r * HW + c;
    float s = 0.f, s2 = 0.f;
    #pragma unroll
    for (int j = 0; j < KP; j++) { s += cs[j]; s2 += cs2[j]; }
    const float inv = 1.f / PS;
    g_sy[idx] = s;
    g_dy[idx] = fabsf(s2 * inv - s * s * inv * inv);
}

// ---------------- Kernel C: correlation + per-patch argmax ----------------------
// grid = (400, 58). block = 512 threads = 8 rows x 64 col-groups of 8 columns.
__global__ void __launch_bounds__(THREADS_C) k_corr(const float* __restrict__ yd) {
    int p = blockIdx.x;
    int r0 = blockIdx.y * ROWS_PER_BLK;
    int tid = threadIdx.x;
    int row_in = tid >> 6;        // 0..7
    int cg = tid & 63;            // 0..63
    int c0 = cg << 3;             // 0..504
    int r = r0 + row_in;
    bool active = (r < HC) && (c0 < HC);

    extern __shared__ float ytile[];          // YROWS * YPITCH
    __shared__ float wpat[576];
    __shared__ unsigned long long red[16];

    float acc[8];
    #pragma unroll
    for (int t = 0; t < 8; t++) acc[t] = 0.f;

    for (int ch = 0; ch < NC; ch++) {
        __syncthreads();
        // patch channel slice -> smem
        for (int e = tid; e < 576; e += THREADS_C)
            wpat[e] = g_patch[p * PS + ch * 576 + e];
        // y tile (rows r0..r0+30, cols 0..487 with 0-pad) -> smem
        const float* yb = yd + ch * IMG;
        for (int e = tid; e < YROWS * YPITCH; e += THREADS_C) {
            int rr = e / YPITCH, cc = e - rr * YPITCH;
            int gr = r0 + rr;
            ytile[e] = (gr < HW && cc < HW) ? yb[gr * HW + cc] : 0.f;
        }
        __syncthreads();

        if (active) {
            #pragma unroll 2
            for (int i = 0; i < KP; i++) {
                const float4* yv = (const float4*)(ytile + (row_in + i) * YPITCH + c0);
                float yw[32];
                #pragma unroll
                for (int q = 0; q < 8; q++) {
                    float4 v = yv[q];
                    yw[4 * q + 0] = v.x; yw[4 * q + 1] = v.y;
                    yw[4 * q + 2] = v.z; yw[4 * q + 3] = v.w;
                }
                const float4* wv = (const float4*)(wpat + i * KP);
                #pragma unroll
                for (int jj = 0; jj < 6; jj++) {
                    float4 w = wv[jj];
                    #pragma unroll
                    for (int t = 0; t < 8; t++) {
                        acc[t] = fmaf(w.x, yw[4 * jj + 0 + t], acc[t]);
                        acc[t] = fmaf(w.y, yw[4 * jj + 1 + t], acc[t]);
                        acc[t] = fmaf(w.z, yw[4 * jj + 2 + t], acc[t]);
                        acc[t] = fmaf(w.w, yw[4 * jj + 3 + t], acc[t]);
                    }
                }
            }
        }
    }

    // epilogue: corr + packed argmax key
    unsigned long long bk = 0ull;
    if (active) {
        float mx = g_meanx[p];
        float dxa = g_denx[p];
        const float invps = 1.f / PS;
        #pragma unroll
        for (int t = 0; t < 8; t++) {
            int c = c0 + t;
            if (c < HC) {
                int pos = r * HC + c;
                float s = g_sy[pos];
                float dya = g_dy[pos];
                float corr = (2.f * (acc[t] - mx * s) * invps + SIGMA) / (dxa + dya + SIGMA);
                unsigned u = __float_as_uint(corr);
                u = (u & 0x80000000u) ? ~u : (u | 0x80000000u);
                unsigned long long key =
                    ((unsigned long long)u << 32) | (unsigned long long)(~(unsigned)pos);
                if (key > bk) bk = key;
            }
        }
    }
    // warp reduce
    #pragma unroll
    for (int off = 16; off > 0; off >>= 1) {
        unsigned long long o = __shfl_down_sync(0xffffffffu, bk, off);
        if (o > bk) bk = o;
    }
    int warp = tid >> 5, lane = tid & 31;
    if (lane == 0) red[warp] = bk;
    __syncthreads();
    if (tid == 0) {
        unsigned long long b = red[0];
        #pragma unroll
        for (int w = 1; w < 16; w++) if (red[w] > b) b = red[w];
        atomicMax(&g_best[p], b);
    }
}

// ---------------- Kernel D: gather winning patches from y, fold to image --------
__global__ void k_gather(const float* __restrict__ y, float* __restrict__ out) {
    int idx = blockIdx.x * blockDim.x + threadIdx.x;
    if (idx >= NC * IMG) return;
    int ch = idx / IMG, rem = idx % IMG;
    int h = rem / HW, w = rem % HW;
    int p = (h / KP) * PGRID + (w / KP);
    unsigned pos = ~((unsigned)(g_best[p] & 0xffffffffull));
    int rp = pos / HC, cp = pos % HC;
    out[idx] = y[ch * IMG + (rp + h % KP) * HW + (cp + w % KP)];
}

extern "C" void kernel_launch(void* const* d_in, const int* in_sizes, int n_in,
                              void* d_out, int out_size) {
    const float* x_dec = (const float*)d_in[0];
    const float* y_dec = (const float*)d_in[1];
    const float* y     = (const float*)d_in[2];
    float* out = (float*)d_out;

    const int smem_c = YROWS * YPITCH * sizeof(float);   // 60512 bytes
    cudaFuncSetAttribute(k_corr, cudaFuncAttributeMaxDynamicSharedMemorySize, smem_c);

    k_prep<<<NP, 256>>>(x_dec);
    k_colsum<<<(HC * HW + 255) / 256, 256>>>(y_dec);
    k_symap<<<(HC * HC + 255) / 256, 256>>>();
    dim3 gc(NP, (HC + ROWS_PER_BLK - 1) / ROWS_PER_BLK);   // (400, 58)
    k_corr<<<gc, THREADS_C, smem_c>>>(y_dec);
    k_gather<<<(NC * IMG + 255) / 256, 256>>>(y, out);
}